// round 10
// baseline (speedup 1.0000x reference)
#include <cuda_runtime.h>
#include <cuda_fp16.h>
#include <math.h>
#include <stdint.h>

#define BN   8
#define CIN  32
#define COUT 32
#define HW   384
#define AUX  128
#define HID  256
#define MODOUT (COUT*CIN*9)   // 9216
#define KDIM 288              // k = tap*32 + ci
#define WST  296              // padded W row stride (conflict-free ldmatrix)

// Scratch (allocation-free rule: __device__ globals)
__device__ float g_bias[BN * COUT];
__device__ __half g_w[BN * COUT * KDIM];   // [n][co][tap*32+ci] fp16

// ---------------------------------------------------------------------------
// warp-MMA helpers (sm_80-class, valid on compute_103 without 'a')
// ---------------------------------------------------------------------------
__device__ __forceinline__ uint32_t smem_u32(const void* p) {
    uint32_t a;
    asm("{ .reg .u64 t; cvta.to.shared.u64 t, %1; cvt.u32.u64 %0, t; }"
        : "=r"(a) : "l"(p));
    return a;
}
__device__ __forceinline__ void ldm4(uint32_t r[4], uint32_t addr) {
    asm volatile("ldmatrix.sync.aligned.m8n8.x4.shared.b16 {%0,%1,%2,%3}, [%4];"
        : "=r"(r[0]), "=r"(r[1]), "=r"(r[2]), "=r"(r[3]) : "r"(addr));
}
__device__ __forceinline__ void mma_f16(float d[4], const uint32_t a[4],
                                        const uint32_t b[2]) {
    asm volatile("mma.sync.aligned.m16n8k16.row.col.f32.f16.f16.f32 "
        "{%0,%1,%2,%3}, {%4,%5,%6,%7}, {%8,%9}, {%0,%1,%2,%3};"
        : "+f"(d[0]), "+f"(d[1]), "+f"(d[2]), "+f"(d[3])
        : "r"(a[0]), "r"(a[1]), "r"(a[2]), "r"(a[3]), "r"(b[0]), "r"(b[1]));
}

// ---------------------------------------------------------------------------
// Fused MLP: grid 73. Blocks 0..71: 128 mod outputs x ALL 8 samples
// (fc_w2 read once chip-wide). Block 72: biases.
// ---------------------------------------------------------------------------
__global__ void mlp_fused(const float* __restrict__ y,
                          const float* __restrict__ weight,
                          const float* __restrict__ fc_w1, const float* __restrict__ fc_b1,
                          const float* __restrict__ fc_a_p,
                          const float* __restrict__ fc_w2, const float* __restrict__ fc_b2,
                          const float* __restrict__ b_w1,  const float* __restrict__ b_b1,
                          const float* __restrict__ b_a_p,
                          const float* __restrict__ b_w2,  const float* __restrict__ b_b2)
{
    __shared__ float y_s[BN * AUX];
    __shared__ float h_s[BN * HID];
    __shared__ float part[256][9];      // padded to kill bank conflicts
    const int t = threadIdx.x;

    #pragma unroll
    for (int i = t; i < BN*AUX; i += 256) y_s[i] = y[i];
    __syncthreads();

    if (blockIdx.x < 72) {
        // ---- hidden layer for all 8 samples (8-way ILP) ----
        {
            float hacc[BN] = {0,0,0,0,0,0,0,0};
            #pragma unroll 4
            for (int i = 0; i < AUX; i++) {
                const float wv = fc_w1[i*HID + t];
                #pragma unroll
                for (int n = 0; n < BN; n++)
                    hacc[n] = fmaf(y_s[n*AUX + i], wv, hacc[n]);
            }
            const float a = *fc_a_p;
            const float b1v = fc_b1[t];
            #pragma unroll
            for (int n = 0; n < BN; n++) {
                const float h = hacc[n] + b1v;
                h_s[n*HID + t] = (h >= 0.f) ? h : a*h;
            }
        }
        __syncthreads();

        // ---- output layer: 128 j, HID split in halves, 8 samples ILP ----
        const int tj = t & 127;
        const int g  = t >> 7;
        const int j  = blockIdx.x * 128 + tj;  // j = co*288 + ci*9 + tap
        const int h0 = g * 128;
        float m[BN] = {0,0,0,0,0,0,0,0};
        #pragma unroll 4
        for (int hh = 0; hh < 128; hh++) {
            const float wv = fc_w2[(h0+hh)*MODOUT + j];
            #pragma unroll
            for (int n = 0; n < BN; n++)
                m[n] = fmaf(h_s[n*HID + h0 + hh], wv, m[n]);
        }
        #pragma unroll
        for (int n = 0; n < BN; n++) part[t][n] = m[n];
        __syncthreads();

        if (t < 128) {
            const float wj = weight[j];
            const float b2 = fc_b2[j];
            const int co  = j / 288;
            const int r   = j - co*288;
            const int ci  = r / 9;
            const int tap = r - ci*9;
            const int kk  = tap*32 + ci;
            #pragma unroll
            for (int n = 0; n < BN; n++) {
                const float mm = part[t][n] + part[t+128][n] + b2;
                const float sg = 1.f / (1.f + expf(-mm));
                g_w[(n*COUT + co)*KDIM + kk] = __float2half_rn(sg * wj);
            }
        }
    } else {
        // ---- bias branch ----
        const float a = *b_a_p;
        {
            float hacc[BN] = {0,0,0,0,0,0,0,0};
            #pragma unroll 4
            for (int i = 0; i < AUX; i++) {
                const float wv = b_w1[i*HID + t];
                #pragma unroll
                for (int n = 0; n < BN; n++)
                    hacc[n] = fmaf(y_s[n*AUX + i], wv, hacc[n]);
            }
            const float b1v = b_b1[t];
            #pragma unroll
            for (int n = 0; n < BN; n++) {
                const float h = hacc[n] + b1v;
                h_s[n*HID + t] = (h >= 0.f) ? h : a*h;
            }
        }
        __syncthreads();

        const int n  = t >> 5;
        const int co = t & 31;
        const float* hb = h_s + n*HID;
        float m0 = 0.f, m1 = 0.f, m2 = 0.f, m3 = 0.f;
        #pragma unroll 4
        for (int hh = 0; hh < HID; hh += 4) {
            m0 = fmaf(hb[hh+0], b_w2[(hh+0)*COUT + co], m0);
            m1 = fmaf(hb[hh+1], b_w2[(hh+1)*COUT + co], m1);
            m2 = fmaf(hb[hh+2], b_w2[(hh+2)*COUT + co], m2);
            m3 = fmaf(hb[hh+3], b_w2[(hh+3)*COUT + co], m3);
        }
        g_bias[n*COUT + co] = (m0 + m1) + (m2 + m3) + b_b2[co];
    }
}

// ---------------------------------------------------------------------------
// Conv: mma.sync fp16 single-pass, 2-row blocking, 3 CTAs/SM.
// B-fragments now via ONE ldmatrix.x4 (non-trans): slab layout [col][ci]
// means row=pixel, contiguous k -> fragment distribution matches mma B
// exactly; 80B row stride is bank-conflict-free.
// ---------------------------------------------------------------------------
#define RC       130
#define CIP      40
#define NSLOT    4
#define SLAB_B   (NSLOT*RC*CIP*2)          // 41600
#define W_BYTES  (COUT*WST*2)              // 18944
#define OFF_W    0
#define OFF_X    (W_BYTES)                 // 18944
#define CONV_SMEM (OFF_X + SLAB_B)         // 60544 -> 3 CTAs/SM
#define NSTG     9                         // ceil(16*RC/256)

__device__ __forceinline__ void stage_row(const float* __restrict__ xn,
                                          uint32_t* __restrict__ xs32,
                                          int gy, int x0, int tid)
{
    const int slot = (gy + NSLOT) & (NSLOT - 1);
    const bool yok = (unsigned)gy < (unsigned)HW;
    float v0[NSTG], v1[NSTG];
    #pragma unroll
    for (int it = 0; it < NSTG; it++) {
        const int i = tid + it*256;
        const int cp  = i / RC;
        const int col = i - cp*RC;
        const int gx  = x0 - 1 + col;
        float f0 = 0.f, f1 = 0.f;
        if (i < 16*RC && yok && (unsigned)gx < (unsigned)HW) {
            const float* p = xn + ((2*cp)*HW + gy)*HW + gx;
            f0 = p[0];
            f1 = p[HW*HW];
        }
        v0[it] = f0; v1[it] = f1;
    }
    #pragma unroll
    for (int it = 0; it < NSTG; it++) {
        const int i = tid + it*256;
        if (i < 16*RC) {
            const int cp  = i / RC;
            const int col = i - cp*RC;
            const __half2 h2 = __floats2half2_rn(v0[it], v1[it]);
            xs32[(slot*RC + col)*(CIP/2) + cp] = *reinterpret_cast<const uint32_t*>(&h2);
        }
    }
}

__global__ void __launch_bounds__(256, 3)
conv_mma(const float* __restrict__ x, float* __restrict__ out)
{
    extern __shared__ char smem[];
    uint32_t* xs32 = reinterpret_cast<uint32_t*>(smem + OFF_X);

    const int tid  = threadIdx.x;
    const int lane = tid & 31;
    const int w    = tid >> 5;
    const int n    = blockIdx.y;
    const int xt   = blockIdx.x % 3;
    const int st   = blockIdx.x / 3;            // 0..36
    const int x0   = xt * 128;
    const int row0  = (st < 7) ? st*12 : 84 + (st-7)*10;
    const int pairs = (st < 7) ? 6 : 5;

    // ---- per-sample weights -> padded smem rows (vectorized u32) ----
    {
        const uint32_t* gw = reinterpret_cast<const uint32_t*>(g_w + (size_t)n*MODOUT);
        uint32_t* ws = reinterpret_cast<uint32_t*>(smem + OFF_W);
        for (int i = tid; i < COUT*(KDIM/2); i += 256) {
            const int co = i / 144, k2 = i - co*144;
            ws[co*(WST/2) + k2] = gw[i];
        }
    }
    const int lanehi = lane >> 2;
    const int laneq2 = (lane & 3) * 2;
    const float bias0 = g_bias[n*COUT + lanehi];
    const float bias1 = g_bias[n*COUT + lanehi + 8];
    const float bias2 = g_bias[n*COUT + lanehi + 16];
    const float bias3 = g_bias[n*COUT + lanehi + 24];

    const float* xn = x + (size_t)n * CIN * HW * HW;
    stage_row(xn, xs32, row0 - 1, x0, tid);
    stage_row(xn, xs32, row0,     x0, tid);
    stage_row(xn, xs32, row0 + 1, x0, tid);
    stage_row(xn, xs32, row0 + 2, x0, tid);
    __syncthreads();

    const uint32_t sb   = smem_u32(smem);
    const uint32_t aoff = (uint32_t)(((lane & 15)*WST + (lane >> 4)*8) * 2);
    const uint32_t wbase = sb + OFF_W + aoff;
    // B ldmatrix lane address: row = pixel (w*16 + lane&7 [+8 for tiles 2,3]),
    // k offset +8 for odd tiles (k8-15)
    const uint32_t xlane = sb + OFF_X +
        (uint32_t)(((w*16 + (lane & 7) + ((lane & 16) ? 8 : 0)) * CIP
                    + ((lane & 8) ? 8 : 0)) * 2);

#define ALOAD(b, kh) do { \
    const uint32_t c32 = (uint32_t)(((kh)*3 + kw)*2 + half) * 32u; \
    ldm4(aA[b][0], wbase + c32); ldm4(aA[b][1], wbase + c32 + 16*WST*2); \
} while (0)

#define BLOAD(b, dd) do { \
    const uint32_t addr = xlane + (uint32_t)((((s_[dd]*RC + kw)*CIP) + hoff) * 2); \
    uint32_t r_[4]; \
    ldm4(r_, addr); \
    bB[b][0][0] = r_[0]; bB[b][0][1] = r_[1]; \
    bB[b][1][0] = r_[2]; bB[b][1][1] = r_[3]; \
} while (0)

#define MMA4(r, ab, bb) do { \
    mma_f16(acc[r][0][0], aA[ab][0], bB[bb][0]); \
    mma_f16(acc[r][1][0], aA[ab][1], bB[bb][0]); \
    mma_f16(acc[r][0][1], aA[ab][0], bB[bb][1]); \
    mma_f16(acc[r][1][1], aA[ab][1], bB[bb][1]); \
} while (0)

    #pragma unroll 1
    for (int t = 0; t < pairs; t++) {
        const int y = row0 + 2*t;
        int s_[4];
        #pragma unroll
        for (int dd = 0; dd < 4; dd++) s_[dd] = (y - 1 + dd) & (NSLOT - 1);

        float acc[2][2][2][4];
        #pragma unroll
        for (int r = 0; r < 2; r++)
            #pragma unroll
            for (int mi = 0; mi < 2; mi++)
                #pragma unroll
                for (int j = 0; j < 2; j++)
                    #pragma unroll
                    for (int q = 0; q < 4; q++) acc[r][mi][j][q] = 0.f;

        #pragma unroll 1
        for (int kwh = 0; kwh < 6; kwh++) {
            const int kw   = kwh >> 1;
            const int half = kwh & 1;
            const int hoff = half * 16;
            uint32_t aA[2][2][4];
            uint32_t bB[2][2][2];

            ALOAD(0, 0);                 // A: kh0
            BLOAD(0, 0);                 // B: d=-1
            ALOAD(1, 1);                 // A: kh1
            BLOAD(1, 1);                 // B: d=0
            MMA4(0, 0, 0);               // row0/kh0 @ d=-1
            BLOAD(0, 2);                 // B: d=1 (reuse buf0)
            MMA4(1, 0, 1);               // row1/kh0 @ d=0
            MMA4(0, 1, 1);               // row0/kh1 @ d=0
            ALOAD(0, 2);                 // A: kh2 (reuse abuf0)
            MMA4(1, 1, 0);               // row1/kh1 @ d=1
            BLOAD(1, 3);                 // B: d=2 (reuse buf1)
            MMA4(0, 0, 0);               // row0/kh2 @ d=1
            MMA4(1, 0, 1);               // row1/kh2 @ d=2
        }

        // ---- epilogue: 2 rows, bias + coalesced float2 stores ----
        #pragma unroll
        for (int r = 0; r < 2; r++) {
            const int yy = y + r;
            const int pxb = x0 + w*16 + laneq2;
            #pragma unroll
            for (int mi = 0; mi < 2; mi++) {
                const float bA = mi ? bias2 : bias0;
                const float bB2 = mi ? bias3 : bias1;
                const int coA = mi*16 + lanehi;
                float* o0 = out + (((size_t)n*COUT + coA)*HW + yy)*HW + pxb;
                #pragma unroll
                for (int j = 0; j < 2; j++) {
                    *reinterpret_cast<float2*>(o0 + 8*j) =
                        make_float2(acc[r][mi][j][0] + bA, acc[r][mi][j][1] + bA);
                    *reinterpret_cast<float2*>(o0 + 8*j + (size_t)8*HW*HW) =
                        make_float2(acc[r][mi][j][2] + bB2, acc[r][mi][j][3] + bB2);
                }
            }
        }

        if (t + 1 < pairs) {
            __syncthreads();
            stage_row(xn, xs32, y + 3, x0, tid);
            stage_row(xn, xs32, y + 4, x0, tid);
            __syncthreads();
        }
    }
#undef ALOAD
#undef BLOAD
#undef MMA4
}

// ---------------------------------------------------------------------------
extern "C" void kernel_launch(void* const* d_in, const int* in_sizes, int n_in,
                              void* d_out, int out_size)
{
    const float* x      = (const float*)d_in[0];
    const float* y      = (const float*)d_in[1];
    const float* weight = (const float*)d_in[2];
    const float* fc_w1  = (const float*)d_in[3];
    const float* fc_b1  = (const float*)d_in[4];
    const float* fc_a   = (const float*)d_in[5];
    const float* fc_w2  = (const float*)d_in[6];
    const float* fc_b2  = (const float*)d_in[7];
    const float* b_w1   = (const float*)d_in[8];
    const float* b_b1   = (const float*)d_in[9];
    const float* b_a    = (const float*)d_in[10];
    const float* b_w2   = (const float*)d_in[11];
    const float* b_b2   = (const float*)d_in[12];
    float* out = (float*)d_out;

    cudaFuncSetAttribute(conv_mma,
                         cudaFuncAttributeMaxDynamicSharedMemorySize,
                         CONV_SMEM);

    mlp_fused<<<73, 256>>>(y, weight, fc_w1, fc_b1, fc_a, fc_w2, fc_b2,
                           b_w1, b_b1, b_a, b_w2, b_b2);
    conv_mma<<<dim3(111, BN), 256, CONV_SMEM>>>(x, out);
}

// round 11
// speedup vs baseline: 1.0858x; 1.0858x over previous
#include <cuda_runtime.h>
#include <cuda_fp16.h>
#include <math.h>
#include <stdint.h>

#define BN   8
#define CIN  32
#define COUT 32
#define HW   384
#define AUX  128
#define HID  256
#define MODOUT (COUT*CIN*9)   // 9216
#define KDIM 288              // k = tap*32 + ci
#define WST  296              // padded W row stride (conflict-free ldmatrix)

// Scratch (allocation-free rule: __device__ globals)
__device__ float g_bias[BN * COUT];
__device__ float g_h[BN * 2 * HID];        // [n][branch][HID]
__device__ __half g_w[BN * COUT * KDIM];   // [n][co][tap*32+ci] fp16

// ---------------------------------------------------------------------------
// warp-MMA helpers (sm_80-class, valid on compute_103 without 'a')
// ---------------------------------------------------------------------------
__device__ __forceinline__ uint32_t smem_u32(const void* p) {
    uint32_t a;
    asm("{ .reg .u64 t; cvta.to.shared.u64 t, %1; cvt.u32.u64 %0, t; }"
        : "=r"(a) : "l"(p));
    return a;
}
__device__ __forceinline__ void ldm4(uint32_t r[4], uint32_t addr) {
    asm volatile("ldmatrix.sync.aligned.m8n8.x4.shared.b16 {%0,%1,%2,%3}, [%4];"
        : "=r"(r[0]), "=r"(r[1]), "=r"(r[2]), "=r"(r[3]) : "r"(addr));
}
__device__ __forceinline__ void mma_f16(float d[4], const uint32_t a[4],
                                        const uint32_t b[2]) {
    asm volatile("mma.sync.aligned.m16n8k16.row.col.f32.f16.f16.f32 "
        "{%0,%1,%2,%3}, {%4,%5,%6,%7}, {%8,%9}, {%0,%1,%2,%3};"
        : "+f"(d[0]), "+f"(d[1]), "+f"(d[2]), "+f"(d[3])
        : "r"(a[0]), "r"(a[1]), "r"(a[2]), "r"(a[3]), "r"(b[0]), "r"(b[1]));
}

// ---------------------------------------------------------------------------
// MLP kernel 1: hidden layers. grid 32 (= 8n x 2branch x 2half), block 128.
// ---------------------------------------------------------------------------
__global__ void mlp_hidden(const float* __restrict__ y,
                           const float* __restrict__ fc_w1, const float* __restrict__ fc_b1,
                           const float* __restrict__ fc_a_p,
                           const float* __restrict__ b_w1,  const float* __restrict__ b_b1,
                           const float* __restrict__ b_a_p)
{
    __shared__ float y_s[AUX];
    const int b  = blockIdx.x;
    const int n  = b >> 2;
    const int br = (b >> 1) & 1;
    const int hf = b & 1;
    const int t  = threadIdx.x;

    y_s[t] = y[n*AUX + t];
    __syncthreads();

    const float* w1 = br ? b_w1 : fc_w1;
    const float* b1 = br ? b_b1 : fc_b1;
    const float  a  = br ? *b_a_p : *fc_a_p;
    const int col = hf*128 + t;

    float acc[8] = {0,0,0,0,0,0,0,0};
    #pragma unroll
    for (int i = 0; i < AUX; i += 8) {
        #pragma unroll
        for (int q = 0; q < 8; q++)
            acc[q] = fmaf(y_s[i+q], w1[(i+q)*HID + col], acc[q]);
    }
    const float h = ((acc[0]+acc[1])+(acc[2]+acc[3]))
                  + ((acc[4]+acc[5])+(acc[6]+acc[7])) + b1[col];
    g_h[(n*2 + br)*HID + col] = (h >= 0.f) ? h : a*h;
}

// ---------------------------------------------------------------------------
// MLP kernel 2: output layers. grid 289, block 512.
// Blocks 0..287: 32 j x 8 samples x 2 HID-halves (fc_w2 read once chip-wide,
// warp-coalesced over j). Block 288: biases.
// ---------------------------------------------------------------------------
__global__ void mlp_out(const float* __restrict__ weight,
                        const float* __restrict__ fc_w2, const float* __restrict__ fc_b2,
                        const float* __restrict__ b_w2,  const float* __restrict__ b_b2)
{
    __shared__ float h_s[BN * HID];
    __shared__ float part[512];
    const int t = threadIdx.x;

    if (blockIdx.x < 288) {
        #pragma unroll
        for (int i = t; i < BN*HID; i += 512)
            h_s[i] = g_h[((i >> 8)*2)*HID + (i & 255)];
        __syncthreads();

        const int hf = t >> 8;              // HID half
        const int tt = t & 255;
        const int n  = tt >> 5;
        const int j  = blockIdx.x*32 + (tt & 31);
        const float* hp = h_s + n*HID + hf*128;
        const float* wp = fc_w2 + (size_t)(hf*128)*MODOUT + j;

        float m[8] = {0,0,0,0,0,0,0,0};
        #pragma unroll 4
        for (int hh = 0; hh < 128; hh += 8) {
            #pragma unroll
            for (int q = 0; q < 8; q++)
                m[q] = fmaf(hp[hh+q], wp[(size_t)(hh+q)*MODOUT], m[q]);
        }
        part[t] = ((m[0]+m[1])+(m[2]+m[3])) + ((m[4]+m[5])+(m[6]+m[7]));
        __syncthreads();

        if (t < 256) {
            const float mm = part[t] + part[t+256] + fc_b2[j];
            const float sg = 1.f / (1.f + expf(-mm));
            const float wm = sg * weight[j];
            const int co  = j / 288;
            const int r   = j - co*288;
            const int ci  = r / 9;
            const int tap = r - ci*9;
            const int nn  = t >> 5;
            g_w[(nn*COUT + co)*KDIM + tap*32 + ci] = __float2half_rn(wm);
        }
    } else {
        #pragma unroll
        for (int i = t; i < BN*HID; i += 512)
            h_s[i] = g_h[((i >> 8)*2 + 1)*HID + (i & 255)];
        __syncthreads();

        if (t < 256) {
            const int n  = t >> 5;
            const int co = t & 31;
            const float* hb = h_s + n*HID;
            float m0 = 0.f, m1 = 0.f, m2 = 0.f, m3 = 0.f;
            #pragma unroll 4
            for (int hh = 0; hh < HID; hh += 4) {
                m0 = fmaf(hb[hh+0], b_w2[(hh+0)*COUT + co], m0);
                m1 = fmaf(hb[hh+1], b_w2[(hh+1)*COUT + co], m1);
                m2 = fmaf(hb[hh+2], b_w2[(hh+2)*COUT + co], m2);
                m3 = fmaf(hb[hh+3], b_w2[(hh+3)*COUT + co], m3);
            }
            g_bias[n*COUT + co] = (m0 + m1) + (m2 + m3) + b_b2[co];
        }
    }
}

// ---------------------------------------------------------------------------
// Conv: mma.sync fp16 single-pass, 2-row blocking, 3 CTAs/SM.
// (unchanged from round 10 — near fallback-HMMA roof)
// ---------------------------------------------------------------------------
#define RC       130
#define CIP      40
#define NSLOT    4
#define SLAB_B   (NSLOT*RC*CIP*2)          // 41600
#define W_BYTES  (COUT*WST*2)              // 18944
#define OFF_W    0
#define OFF_X    (W_BYTES)                 // 18944
#define CONV_SMEM (OFF_X + SLAB_B)         // 60544 -> 3 CTAs/SM
#define NSTG     9                         // ceil(16*RC/256)

__device__ __forceinline__ void stage_row(const float* __restrict__ xn,
                                          uint32_t* __restrict__ xs32,
                                          int gy, int x0, int tid)
{
    const int slot = (gy + NSLOT) & (NSLOT - 1);
    const bool yok = (unsigned)gy < (unsigned)HW;
    float v0[NSTG], v1[NSTG];
    #pragma unroll
    for (int it = 0; it < NSTG; it++) {
        const int i = tid + it*256;
        const int cp  = i / RC;
        const int col = i - cp*RC;
        const int gx  = x0 - 1 + col;
        float f0 = 0.f, f1 = 0.f;
        if (i < 16*RC && yok && (unsigned)gx < (unsigned)HW) {
            const float* p = xn + ((2*cp)*HW + gy)*HW + gx;
            f0 = p[0];
            f1 = p[HW*HW];
        }
        v0[it] = f0; v1[it] = f1;
    }
    #pragma unroll
    for (int it = 0; it < NSTG; it++) {
        const int i = tid + it*256;
        if (i < 16*RC) {
            const int cp  = i / RC;
            const int col = i - cp*RC;
            const __half2 h2 = __floats2half2_rn(v0[it], v1[it]);
            xs32[(slot*RC + col)*(CIP/2) + cp] = *reinterpret_cast<const uint32_t*>(&h2);
        }
    }
}

__global__ void __launch_bounds__(256, 3)
conv_mma(const float* __restrict__ x, float* __restrict__ out)
{
    extern __shared__ char smem[];
    uint32_t* xs32 = reinterpret_cast<uint32_t*>(smem + OFF_X);

    const int tid  = threadIdx.x;
    const int lane = tid & 31;
    const int w    = tid >> 5;
    const int n    = blockIdx.y;
    const int xt   = blockIdx.x % 3;
    const int st   = blockIdx.x / 3;            // 0..36
    const int x0   = xt * 128;
    const int row0  = (st < 7) ? st*12 : 84 + (st-7)*10;
    const int pairs = (st < 7) ? 6 : 5;

    // ---- per-sample weights -> padded smem rows (vectorized u32) ----
    {
        const uint32_t* gw = reinterpret_cast<const uint32_t*>(g_w + (size_t)n*MODOUT);
        uint32_t* ws = reinterpret_cast<uint32_t*>(smem + OFF_W);
        for (int i = tid; i < COUT*(KDIM/2); i += 256) {
            const int co = i / 144, k2 = i - co*144;
            ws[co*(WST/2) + k2] = gw[i];
        }
    }
    const int lanehi = lane >> 2;
    const int laneq2 = (lane & 3) * 2;
    const float bias0 = g_bias[n*COUT + lanehi];
    const float bias1 = g_bias[n*COUT + lanehi + 8];
    const float bias2 = g_bias[n*COUT + lanehi + 16];
    const float bias3 = g_bias[n*COUT + lanehi + 24];

    const float* xn = x + (size_t)n * CIN * HW * HW;
    stage_row(xn, xs32, row0 - 1, x0, tid);
    stage_row(xn, xs32, row0,     x0, tid);
    stage_row(xn, xs32, row0 + 1, x0, tid);
    stage_row(xn, xs32, row0 + 2, x0, tid);
    __syncthreads();

    const uint32_t sb   = smem_u32(smem);
    const uint32_t aoff = (uint32_t)(((lane & 15)*WST + (lane >> 4)*8) * 2);
    const uint32_t wbase = sb + OFF_W + aoff;
    const uint32_t xlane = sb + OFF_X +
        (uint32_t)(((w*16 + (lane & 7) + ((lane & 16) ? 8 : 0)) * CIP
                    + ((lane & 8) ? 8 : 0)) * 2);

#define ALOAD(b, kh) do { \
    const uint32_t c32 = (uint32_t)(((kh)*3 + kw)*2 + half) * 32u; \
    ldm4(aA[b][0], wbase + c32); ldm4(aA[b][1], wbase + c32 + 16*WST*2); \
} while (0)

#define BLOAD(b, dd) do { \
    const uint32_t addr = xlane + (uint32_t)((((s_[dd]*RC + kw)*CIP) + hoff) * 2); \
    uint32_t r_[4]; \
    ldm4(r_, addr); \
    bB[b][0][0] = r_[0]; bB[b][0][1] = r_[1]; \
    bB[b][1][0] = r_[2]; bB[b][1][1] = r_[3]; \
} while (0)

#define MMA4(r, ab, bb) do { \
    mma_f16(acc[r][0][0], aA[ab][0], bB[bb][0]); \
    mma_f16(acc[r][1][0], aA[ab][1], bB[bb][0]); \
    mma_f16(acc[r][0][1], aA[ab][0], bB[bb][1]); \
    mma_f16(acc[r][1][1], aA[ab][1], bB[bb][1]); \
} while (0)

    #pragma unroll 1
    for (int t = 0; t < pairs; t++) {
        const int y = row0 + 2*t;
        int s_[4];
        #pragma unroll
        for (int dd = 0; dd < 4; dd++) s_[dd] = (y - 1 + dd) & (NSLOT - 1);

        float acc[2][2][2][4];
        #pragma unroll
        for (int r = 0; r < 2; r++)
            #pragma unroll
            for (int mi = 0; mi < 2; mi++)
                #pragma unroll
                for (int j = 0; j < 2; j++)
                    #pragma unroll
                    for (int q = 0; q < 4; q++) acc[r][mi][j][q] = 0.f;

        #pragma unroll 1
        for (int kwh = 0; kwh < 6; kwh++) {
            const int kw   = kwh >> 1;
            const int half = kwh & 1;
            const int hoff = half * 16;
            uint32_t aA[2][2][4];
            uint32_t bB[2][2][2];

            ALOAD(0, 0);                 // A: kh0
            BLOAD(0, 0);                 // B: d=-1
            ALOAD(1, 1);                 // A: kh1
            BLOAD(1, 1);                 // B: d=0
            MMA4(0, 0, 0);               // row0/kh0 @ d=-1
            BLOAD(0, 2);                 // B: d=1 (reuse buf0)
            MMA4(1, 0, 1);               // row1/kh0 @ d=0
            MMA4(0, 1, 1);               // row0/kh1 @ d=0
            ALOAD(0, 2);                 // A: kh2 (reuse abuf0)
            MMA4(1, 1, 0);               // row1/kh1 @ d=1
            BLOAD(1, 3);                 // B: d=2 (reuse buf1)
            MMA4(0, 0, 0);               // row0/kh2 @ d=1
            MMA4(1, 0, 1);               // row1/kh2 @ d=2
        }

        // ---- epilogue: 2 rows, bias + coalesced float2 stores ----
        #pragma unroll
        for (int r = 0; r < 2; r++) {
            const int yy = y + r;
            const int pxb = x0 + w*16 + laneq2;
            #pragma unroll
            for (int mi = 0; mi < 2; mi++) {
                const float bA = mi ? bias2 : bias0;
                const float bB2 = mi ? bias3 : bias1;
                const int coA = mi*16 + lanehi;
                float* o0 = out + (((size_t)n*COUT + coA)*HW + yy)*HW + pxb;
                #pragma unroll
                for (int j = 0; j < 2; j++) {
                    *reinterpret_cast<float2*>(o0 + 8*j) =
                        make_float2(acc[r][mi][j][0] + bA, acc[r][mi][j][1] + bA);
                    *reinterpret_cast<float2*>(o0 + 8*j + (size_t)8*HW*HW) =
                        make_float2(acc[r][mi][j][2] + bB2, acc[r][mi][j][3] + bB2);
                }
            }
        }

        if (t + 1 < pairs) {
            __syncthreads();
            stage_row(xn, xs32, y + 3, x0, tid);
            stage_row(xn, xs32, y + 4, x0, tid);
            __syncthreads();
        }
    }
#undef ALOAD
#undef BLOAD
#undef MMA4
}

// ---------------------------------------------------------------------------
extern "C" void kernel_launch(void* const* d_in, const int* in_sizes, int n_in,
                              void* d_out, int out_size)
{
    const float* x      = (const float*)d_in[0];
    const float* y      = (const float*)d_in[1];
    const float* weight = (const float*)d_in[2];
    const float* fc_w1  = (const float*)d_in[3];
    const float* fc_b1  = (const float*)d_in[4];
    const float* fc_a   = (const float*)d_in[5];
    const float* fc_w2  = (const float*)d_in[6];
    const float* fc_b2  = (const float*)d_in[7];
    const float* b_w1   = (const float*)d_in[8];
    const float* b_b1   = (const float*)d_in[9];
    const float* b_a    = (const float*)d_in[10];
    const float* b_w2   = (const float*)d_in[11];
    const float* b_b2   = (const float*)d_in[12];
    float* out = (float*)d_out;

    cudaFuncSetAttribute(conv_mma,
                         cudaFuncAttributeMaxDynamicSharedMemorySize,
                         CONV_SMEM);

    mlp_hidden<<<32, 128>>>(y, fc_w1, fc_b1, fc_a, b_w1, b_b1, b_a);
    mlp_out<<<289, 512>>>(weight, fc_w2, fc_b2, b_w2, b_b2);
    conv_mma<<<dim3(111, BN), 256, CONV_SMEM>>>(x, out);
}

// round 12
// speedup vs baseline: 1.1283x; 1.0391x over previous
#include <cuda_runtime.h>
#include <cuda_fp16.h>
#include <math.h>
#include <stdint.h>

#define BN   8
#define CIN  32
#define COUT 32
#define HW   384
#define AUX  128
#define HID  256
#define MODOUT (COUT*CIN*9)   // 9216
#define KDIM 288              // k = tap*32 + ci
#define WST  296              // padded W row stride (conflict-free ldmatrix)

// Scratch (allocation-free rule: __device__ globals)
__device__ float g_bias[BN * COUT];
__device__ float g_h[BN * 2 * HID];        // [n][branch][HID]
__device__ __half g_w[BN * COUT * KDIM];   // [n][co][tap*32+ci] fp16

// ---------------------------------------------------------------------------
// warp-MMA helpers (sm_80-class, valid on compute_103 without 'a')
// ---------------------------------------------------------------------------
__device__ __forceinline__ uint32_t smem_u32(const void* p) {
    uint32_t a;
    asm("{ .reg .u64 t; cvta.to.shared.u64 t, %1; cvt.u32.u64 %0, t; }"
        : "=r"(a) : "l"(p));
    return a;
}
__device__ __forceinline__ void ldm4(uint32_t r[4], uint32_t addr) {
    asm volatile("ldmatrix.sync.aligned.m8n8.x4.shared.b16 {%0,%1,%2,%3}, [%4];"
        : "=r"(r[0]), "=r"(r[1]), "=r"(r[2]), "=r"(r[3]) : "r"(addr));
}
__device__ __forceinline__ void mma_f16(float d[4], const uint32_t a[4],
                                        const uint32_t b[2]) {
    asm volatile("mma.sync.aligned.m16n8k16.row.col.f32.f16.f16.f32 "
        "{%0,%1,%2,%3}, {%4,%5,%6,%7}, {%8,%9}, {%0,%1,%2,%3};"
        : "+f"(d[0]), "+f"(d[1]), "+f"(d[2]), "+f"(d[3])
        : "r"(a[0]), "r"(a[1]), "r"(a[2]), "r"(a[3]), "r"(b[0]), "r"(b[1]));
}

// ---------------------------------------------------------------------------
// MLP kernel 1: hidden layers. grid 32 (= 8n x 2branch x 2half), block 128.
// ILP-16 over the AUX reduction.
// ---------------------------------------------------------------------------
__global__ void mlp_hidden(const float* __restrict__ y,
                           const float* __restrict__ fc_w1, const float* __restrict__ fc_b1,
                           const float* __restrict__ fc_a_p,
                           const float* __restrict__ b_w1,  const float* __restrict__ b_b1,
                           const float* __restrict__ b_a_p)
{
    __shared__ float y_s[AUX];
    const int b  = blockIdx.x;
    const int n  = b >> 2;
    const int br = (b >> 1) & 1;
    const int hf = b & 1;
    const int t  = threadIdx.x;

    y_s[t] = y[n*AUX + t];
    __syncthreads();

    const float* w1 = br ? b_w1 : fc_w1;
    const float* b1 = br ? b_b1 : fc_b1;
    const float  a  = br ? *b_a_p : *fc_a_p;
    const int col = hf*128 + t;

    float acc[16];
    #pragma unroll
    for (int q = 0; q < 16; q++) acc[q] = 0.f;
    #pragma unroll
    for (int i = 0; i < AUX; i += 16) {
        #pragma unroll
        for (int q = 0; q < 16; q++)
            acc[q] = fmaf(y_s[i+q], w1[(i+q)*HID + col], acc[q]);
    }
    float s = 0.f;
    #pragma unroll
    for (int q = 0; q < 16; q++) s += acc[q];
    const float h = s + b1[col];
    g_h[(n*2 + br)*HID + col] = (h >= 0.f) ? h : a*h;
}

// ---------------------------------------------------------------------------
// MLP kernel 2: output layers. grid 289, block 512, ILP-16.
// ---------------------------------------------------------------------------
__global__ void mlp_out(const float* __restrict__ weight,
                        const float* __restrict__ fc_w2, const float* __restrict__ fc_b2,
                        const float* __restrict__ b_w2,  const float* __restrict__ b_b2)
{
    __shared__ float h_s[BN * HID];
    __shared__ float part[512];
    const int t = threadIdx.x;

    if (blockIdx.x < 288) {
        #pragma unroll
        for (int i = t; i < BN*HID; i += 512)
            h_s[i] = g_h[((i >> 8)*2)*HID + (i & 255)];
        __syncthreads();

        const int hf = t >> 8;              // HID half
        const int tt = t & 255;
        const int n  = tt >> 5;
        const int j  = blockIdx.x*32 + (tt & 31);
        const float* hp = h_s + n*HID + hf*128;
        const float* wp = fc_w2 + (size_t)(hf*128)*MODOUT + j;

        float m[16];
        #pragma unroll
        for (int q = 0; q < 16; q++) m[q] = 0.f;
        #pragma unroll
        for (int hh = 0; hh < 128; hh += 16) {
            #pragma unroll
            for (int q = 0; q < 16; q++)
                m[q] = fmaf(hp[hh+q], wp[(size_t)(hh+q)*MODOUT], m[q]);
        }
        float s = 0.f;
        #pragma unroll
        for (int q = 0; q < 16; q++) s += m[q];
        part[t] = s;
        __syncthreads();

        if (t < 256) {
            const float mm = part[t] + part[t+256] + fc_b2[j];
            const float sg = 1.f / (1.f + expf(-mm));
            const float wm = sg * weight[j];
            const int co  = j / 288;
            const int r   = j - co*288;
            const int ci  = r / 9;
            const int tap = r - ci*9;
            const int nn  = t >> 5;
            g_w[(nn*COUT + co)*KDIM + tap*32 + ci] = __float2half_rn(wm);
        }
    } else {
        #pragma unroll
        for (int i = t; i < BN*HID; i += 512)
            h_s[i] = g_h[((i >> 8)*2 + 1)*HID + (i & 255)];
        __syncthreads();

        if (t < 256) {
            const int n  = t >> 5;
            const int co = t & 31;
            const float* hb = h_s + n*HID;
            float m[8];
            #pragma unroll
            for (int q = 0; q < 8; q++) m[q] = 0.f;
            #pragma unroll
            for (int hh = 0; hh < HID; hh += 8) {
                #pragma unroll
                for (int q = 0; q < 8; q++)
                    m[q] = fmaf(hb[hh+q], b_w2[(hh+q)*COUT + co], m[q]);
            }
            float s = 0.f;
            #pragma unroll
            for (int q = 0; q < 8; q++) s += m[q];
            g_bias[n*COUT + co] = s + b_b2[co];
        }
    }
}

// ---------------------------------------------------------------------------
// Conv: mma.sync fp16 single-pass, 2-row blocking, 3 CTAs/SM,
// cross-kwh SOFTWARE PIPELINE: every ldmatrix is consumed >=2 MMA4 groups
// later; kwh5 tail preloads the next pair's first A/B fragments.
// ---------------------------------------------------------------------------
#define RC       130
#define CIP      40
#define NSLOT    4
#define SLAB_B   (NSLOT*RC*CIP*2)          // 41600
#define W_BYTES  (COUT*WST*2)              // 18944
#define OFF_W    0
#define OFF_X    (W_BYTES)                 // 18944
#define CONV_SMEM (OFF_X + SLAB_B)         // 60544 -> 3 CTAs/SM
#define NSTG     9                         // ceil(16*RC/256)

__device__ __forceinline__ void stage_row(const float* __restrict__ xn,
                                          uint32_t* __restrict__ xs32,
                                          int gy, int x0, int tid)
{
    const int slot = (gy + NSLOT) & (NSLOT - 1);
    const bool yok = (unsigned)gy < (unsigned)HW;
    float v0[NSTG], v1[NSTG];
    #pragma unroll
    for (int it = 0; it < NSTG; it++) {
        const int i = tid + it*256;
        const int cp  = i / RC;
        const int col = i - cp*RC;
        const int gx  = x0 - 1 + col;
        float f0 = 0.f, f1 = 0.f;
        if (i < 16*RC && yok && (unsigned)gx < (unsigned)HW) {
            const float* p = xn + ((2*cp)*HW + gy)*HW + gx;
            f0 = p[0];
            f1 = p[HW*HW];
        }
        v0[it] = f0; v1[it] = f1;
    }
    #pragma unroll
    for (int it = 0; it < NSTG; it++) {
        const int i = tid + it*256;
        if (i < 16*RC) {
            const int cp  = i / RC;
            const int col = i - cp*RC;
            const __half2 h2 = __floats2half2_rn(v0[it], v1[it]);
            xs32[(slot*RC + col)*(CIP/2) + cp] = *reinterpret_cast<const uint32_t*>(&h2);
        }
    }
}

__global__ void __launch_bounds__(256, 3)
conv_mma(const float* __restrict__ x, float* __restrict__ out)
{
    extern __shared__ char smem[];
    uint32_t* xs32 = reinterpret_cast<uint32_t*>(smem + OFF_X);

    const int tid  = threadIdx.x;
    const int lane = tid & 31;
    const int w    = tid >> 5;
    const int n    = blockIdx.y;
    const int xt   = blockIdx.x % 3;
    const int st   = blockIdx.x / 3;            // 0..36
    const int x0   = xt * 128;
    const int row0  = (st < 7) ? st*12 : 84 + (st-7)*10;
    const int pairs = (st < 7) ? 6 : 5;

    // ---- per-sample weights -> padded smem rows (vectorized u32) ----
    {
        const uint32_t* gw = reinterpret_cast<const uint32_t*>(g_w + (size_t)n*MODOUT);
        uint32_t* ws = reinterpret_cast<uint32_t*>(smem + OFF_W);
        for (int i = tid; i < COUT*(KDIM/2); i += 256) {
            const int co = i / 144, k2 = i - co*144;
            ws[co*(WST/2) + k2] = gw[i];
        }
    }
    const int lanehi = lane >> 2;
    const int laneq2 = (lane & 3) * 2;
    const float bias0 = g_bias[n*COUT + lanehi];
    const float bias1 = g_bias[n*COUT + lanehi + 8];
    const float bias2 = g_bias[n*COUT + lanehi + 16];
    const float bias3 = g_bias[n*COUT + lanehi + 24];

    const float* xn = x + (size_t)n * CIN * HW * HW;
    stage_row(xn, xs32, row0 - 1, x0, tid);
    stage_row(xn, xs32, row0,     x0, tid);
    stage_row(xn, xs32, row0 + 1, x0, tid);
    stage_row(xn, xs32, row0 + 2, x0, tid);
    __syncthreads();

    const uint32_t sb   = smem_u32(smem);
    const uint32_t aoff = (uint32_t)(((lane & 15)*WST + (lane >> 4)*8) * 2);
    const uint32_t wbase = sb + OFF_W + aoff;
    const uint32_t xlane = sb + OFF_X +
        (uint32_t)(((w*16 + (lane & 7) + ((lane & 16) ? 8 : 0)) * CIP
                    + ((lane & 8) ? 8 : 0)) * 2);

    uint32_t aA[2][2][4];       // [buf][m-tile][regs]
    uint32_t bB[2][4];          // [buf][regs]: j0 = +0, j1 = +2

#define ALOADX(b, kh, kw, hf) do { \
    const uint32_t c32_ = (uint32_t)(((((kh)*3+(kw))*2+(hf))) * 32u); \
    ldm4(aA[b][0], wbase + c32_); \
    ldm4(aA[b][1], wbase + c32_ + 16*WST*2); \
} while (0)

#define BLOADX(b, slot, kw, hf) do { \
    const uint32_t addr_ = xlane + \
        (uint32_t)(((((slot)*RC + (kw))*CIP) + (hf)*16) * 2); \
    ldm4(bB[b], addr_); \
} while (0)

#define MMA4(r, ab, bb) do { \
    mma_f16(acc[r][0][0], aA[ab][0], bB[bb]); \
    mma_f16(acc[r][1][0], aA[ab][1], bB[bb]); \
    mma_f16(acc[r][0][1], aA[ab][0], bB[bb]+2); \
    mma_f16(acc[r][1][1], aA[ab][1], bB[bb]+2); \
} while (0)

// Pipelined kwh body. Entry: aA[ain]=kh0@(kw,hf), bB[0]=d0@(kw,hf).
// Exit: aA[aot]=kh0@(nkw,nhf), bB[0]=d0-next (@nslot).
#define KWH_BODY(ain, aot, kw, hf, nkw, nhf, nslot) do { \
    BLOADX(1, s_[1], kw, hf);        /* d1 */ \
    ALOADX(aot, 1, kw, hf);          /* kh1 */ \
    MMA4(0, ain, 0);                 /* row0/kh0 @ d0 */ \
    BLOADX(0, s_[2], kw, hf);        /* d2 */ \
    MMA4(1, ain, 1);                 /* row1/kh0 @ d1 */ \
    ALOADX(ain, 2, kw, hf);          /* kh2 */ \
    MMA4(0, aot, 1);                 /* row0/kh1 @ d1 */ \
    BLOADX(1, s_[3], kw, hf);        /* d3 */ \
    MMA4(1, aot, 0);                 /* row1/kh1 @ d2 */ \
    ALOADX(aot, 0, nkw, nhf);        /* next kh0 */ \
    MMA4(0, ain, 0);                 /* row0/kh2 @ d2 */ \
    BLOADX(0, nslot, nkw, nhf);      /* next d0 */ \
    MMA4(1, ain, 1);                 /* row1/kh2 @ d3 */ \
} while (0)

    // strip prologue: first pair's kwh0 entry fragments
    ALOADX(0, 0, 0, 0);
    BLOADX(0, (row0 - 1) & (NSLOT - 1), 0, 0);

    #pragma unroll 1
    for (int t = 0; t < pairs; t++) {
        const int y = row0 + 2*t;
        int s_[4];
        #pragma unroll
        for (int dd = 0; dd < 4; dd++) s_[dd] = (y - 1 + dd) & (NSLOT - 1);

        float acc[2][2][2][4];
        #pragma unroll
        for (int r = 0; r < 2; r++)
            #pragma unroll
            for (int mi = 0; mi < 2; mi++)
                #pragma unroll
                for (int j = 0; j < 2; j++)
                    #pragma unroll
                    for (int q = 0; q < 4; q++) acc[r][mi][j][q] = 0.f;

        // 6 kwh bodies, A-buffer parity alternating; kwh5 tail preloads
        // next pair's kwh0 fragments (next d0 slot = s_[2] = (y+1)&3).
        KWH_BODY(0, 1, 0, 0, 0, 1, s_[0]);
        KWH_BODY(1, 0, 0, 1, 1, 0, s_[0]);
        KWH_BODY(0, 1, 1, 0, 1, 1, s_[0]);
        KWH_BODY(1, 0, 1, 1, 2, 0, s_[0]);
        KWH_BODY(0, 1, 2, 0, 2, 1, s_[0]);
        KWH_BODY(1, 0, 2, 1, 0, 0, s_[2]);

        // ---- epilogue: 2 rows, bias + coalesced float2 stores ----
        #pragma unroll
        for (int r = 0; r < 2; r++) {
            const int yy = y + r;
            const int pxb = x0 + w*16 + laneq2;
            #pragma unroll
            for (int mi = 0; mi < 2; mi++) {
                const float bA = mi ? bias2 : bias0;
                const float bB2 = mi ? bias3 : bias1;
                const int coA = mi*16 + lanehi;
                float* o0 = out + (((size_t)n*COUT + coA)*HW + yy)*HW + pxb;
                #pragma unroll
                for (int j = 0; j < 2; j++) {
                    *reinterpret_cast<float2*>(o0 + 8*j) =
                        make_float2(acc[r][mi][j][0] + bA, acc[r][mi][j][1] + bA);
                    *reinterpret_cast<float2*>(o0 + 8*j + (size_t)8*HW*HW) =
                        make_float2(acc[r][mi][j][2] + bB2, acc[r][mi][j][3] + bB2);
                }
            }
        }

        if (t + 1 < pairs) {
            __syncthreads();
            stage_row(xn, xs32, y + 3, x0, tid);
            stage_row(xn, xs32, y + 4, x0, tid);
            __syncthreads();
        }
    }
#undef ALOADX
#undef BLOADX
#undef MMA4
#undef KWH_BODY
}

// ---------------------------------------------------------------------------
extern "C" void kernel_launch(void* const* d_in, const int* in_sizes, int n_in,
                              void* d_out, int out_size)
{
    const float* x      = (const float*)d_in[0];
    const float* y      = (const float*)d_in[1];
    const float* weight = (const float*)d_in[2];
    const float* fc_w1  = (const float*)d_in[3];
    const float* fc_b1  = (const float*)d_in[4];
    const float* fc_a   = (const float*)d_in[5];
    const float* fc_w2  = (const float*)d_in[6];
    const float* fc_b2  = (const float*)d_in[7];
    const float* b_w1   = (const float*)d_in[8];
    const float* b_b1   = (const float*)d_in[9];
    const float* b_a    = (const float*)d_in[10];
    const float* b_w2   = (const float*)d_in[11];
    const float* b_b2   = (const float*)d_in[12];
    float* out = (float*)d_out;

    cudaFuncSetAttribute(conv_mma,
                         cudaFuncAttributeMaxDynamicSharedMemorySize,
                         CONV_SMEM);

    mlp_hidden<<<32, 128>>>(y, fc_w1, fc_b1, fc_a, b_w1, b_b1, b_a);
    mlp_out<<<289, 512>>>(weight, fc_w2, fc_b2, b_w2, b_b2);
    conv_mma<<<dim3(111, BN), 256, CONV_SMEM>>>(x, out);
}